// round 16
// baseline (speedup 1.0000x reference)
#include <cuda_runtime.h>
#include <cuda_bf16.h>
#include <cstdint>

// Fixed problem shapes: E<=4096, IN=OUT=256, N_NODES=1024
#define MAX_E 4096
#define NN    1024
#define FC    256
#define FC4   64
#define NT    256

// ---------------- global scratch ----------------
__device__ int   g_hist[NN];    // src count low 16 bits, dst count high 16 bits
__device__ int   g_sl[NN];      // self-loop count
__device__ int   g_flags;       // bit0: any nonzero byte, bit1: misaligned nonzero (sticky)
__device__ float g_w[MAX_E];
__device__ float g_t[NN * FC];
__device__ float g_T[NN * FC];

__device__ __forceinline__ void red_add_v4(float* p, float a, float b,
                                           float c, float d) {
    asm volatile("red.global.add.v4.f32 [%0], {%1, %2, %3, %4};"
                 :: "l"(p), "f"(a), "f"(b), "f"(c), "f"(d)
                 : "memory");
}

// ============ K0: zero accumulators + hist scratch (replay-safe) ===========
__global__ __launch_bounds__(NT)
void k_zero() {
    int i = blockIdx.x * NT + threadIdx.x;          // 256 blocks -> 65536
    ((float4*)g_t)[i] = make_float4(0.f, 0.f, 0.f, 0.f);
    if (i < NN) { g_hist[i] = 0; g_sl[i] = 0; }
}

// ============ K1: global histogram + layout flags ==========================
__global__ __launch_bounds__(NT)
void k_hist(const int* __restrict__ ei, const unsigned char* __restrict__ bb,
            int E) {
    int e = blockIdx.x * NT + threadIdx.x;
    if (e >= E) return;
    int s = ei[e], d = ei[E + e];
    atomicAdd(&g_hist[s], 1);
    atomicAdd(&g_hist[d], 0x10000);
    if (s == d) atomicAdd(&g_sl[s], 1);
    unsigned char v = bb[e];
    if (v) atomicOr(&g_flags, (e & 3) ? 3 : 1);
}

// ============ K2: scatter  t[src] -= w*x, t[dst] += w*x  (v4 REDs) =========
__global__ __launch_bounds__(NT)
void k_scatter(const float* __restrict__ x, const int* __restrict__ ei,
               const unsigned char* __restrict__ bb, int E) {
    int i = blockIdx.x * NT + threadIdx.x;
    if (i >= E * FC4) return;
    int e  = i >> 6;
    int c4 = i & 63;

    int s = ei[e], d = ei[E + e];           // warp-uniform loads (broadcast)
    float w = 0.0f;
    if (s != d) {
        int hs = g_hist[s], hd = g_hist[d];
        int deg = (hs & 0xffff) + (hs >> 16)
                + (hd & 0xffff) + (hd >> 16)
                - 2 * (g_sl[s] + g_sl[d]);
        int flags = g_flags;
        int dir;
        if (flags & 2)      dir = bb[e] != 0;               // byte layout
        else if (flags & 1) dir = ((const int*)bb)[e] != 0; // int layout
        else                dir = 0;
        w = (dir ? -1.0f : 1.0f) * rsqrtf((float)deg);
    }
    if (c4 == 0) g_w[e] = w;
    if (w == 0.0f) return;

    float4 v = ((const float4*)x)[e * FC4 + c4];
    float* ps = &g_t[(size_t)s * FC + c4 * 4];
    float* pd = &g_t[(size_t)d * FC + c4 * 4];
    red_add_v4(ps, -w * v.x, -w * v.y, -w * v.z, -w * v.w);
    red_add_v4(pd,  w * v.x,  w * v.y,  w * v.z,  w * v.w);
}

// ============ K3: GEMM  T = t @ W^T  via bf16-split tensor cores ===========
// 128 blocks x 256 threads (8 warps). Tile 32x64, K chunked by 64.
// D = Ah*Bh + Ah*Bl + Al*Bh in fp32 accumulators (AlBl dropped, ~2^-18 rel).
#define KC   64            // k-chunk
#define BSTR 72            // smem row stride in bf16 (36 words; 36%32=4 -> conflict-free frags)

__device__ __forceinline__ void mma_bf16(float c[4], uint32_t a0, uint32_t a1,
                                         uint32_t a2, uint32_t a3,
                                         uint32_t b0, uint32_t b1) {
    asm volatile(
        "mma.sync.aligned.m16n8k16.row.col.f32.bf16.bf16.f32 "
        "{%0,%1,%2,%3}, {%4,%5,%6,%7}, {%8,%9}, {%0,%1,%2,%3};"
        : "+f"(c[0]), "+f"(c[1]), "+f"(c[2]), "+f"(c[3])
        : "r"(a0), "r"(a1), "r"(a2), "r"(a3), "r"(b0), "r"(b1));
}

__device__ __forceinline__ void split_bf16(float v, __nv_bfloat16& h,
                                           __nv_bfloat16& l) {
    h = __float2bfloat16(v);
    l = __float2bfloat16(v - __bfloat162float(h));
}

__global__ __launch_bounds__(256)
void k_gemm(const float* __restrict__ W) {
    __shared__ __nv_bfloat16 Ah[32][BSTR], Al[32][BSTR];
    __shared__ __nv_bfloat16 Bh[64][BSTR], Bl[64][BSTR];

    const int tid  = threadIdx.x;
    const int b    = blockIdx.x;
    const int gx   = b & 3, gy = b >> 2;
    const int m0   = gy * 32, n0 = gx * 64;
    const int wid  = tid >> 5;
    const int lane = tid & 31;
    const int wm   = wid >> 2;          // 0..1 : 16-row slab
    const int wn   = wid & 3;           // 0..3 : 16-col slab

    float acc0[4] = {0.f, 0.f, 0.f, 0.f};   // n8 slab 0
    float acc1[4] = {0.f, 0.f, 0.f, 0.f};   // n8 slab 1

    for (int kc = 0; kc < FC; kc += KC) {
        // ---- load + split A chunk: 32 x 64 fp32 = 512 float4, 2/thread ----
        #pragma unroll
        for (int r = 0; r < 2; r++) {
            int idx = tid + 256 * r;
            int row = idx >> 4;             // 16 float4 per row
            int kq  = (idx & 15) << 2;
            float4 v = *(const float4*)&g_t[(m0 + row) * FC + kc + kq];
            __nv_bfloat16 h0, l0, h1, l1, h2, l2, h3, l3;
            split_bf16(v.x, h0, l0); split_bf16(v.y, h1, l1);
            split_bf16(v.z, h2, l2); split_bf16(v.w, h3, l3);
            Ah[row][kq + 0] = h0; Ah[row][kq + 1] = h1;
            Ah[row][kq + 2] = h2; Ah[row][kq + 3] = h3;
            Al[row][kq + 0] = l0; Al[row][kq + 1] = l1;
            Al[row][kq + 2] = l2; Al[row][kq + 3] = l3;
        }
        // ---- load + split B chunk: 64 x 64 fp32 = 1024 float4, 4/thread ---
        #pragma unroll
        for (int r = 0; r < 4; r++) {
            int idx = tid + 256 * r;
            int n   = idx >> 4;
            int kq  = (idx & 15) << 2;
            float4 v = *(const float4*)&W[(n0 + n) * FC + kc + kq];
            __nv_bfloat16 h0, l0, h1, l1, h2, l2, h3, l3;
            split_bf16(v.x, h0, l0); split_bf16(v.y, h1, l1);
            split_bf16(v.z, h2, l2); split_bf16(v.w, h3, l3);
            Bh[n][kq + 0] = h0; Bh[n][kq + 1] = h1;
            Bh[n][kq + 2] = h2; Bh[n][kq + 3] = h3;
            Bl[n][kq + 0] = l0; Bl[n][kq + 1] = l1;
            Bl[n][kq + 2] = l2; Bl[n][kq + 3] = l3;
        }
        __syncthreads();

        // ---- mma over 4 k16 steps ----
        const int r0 = wm * 16 + (lane >> 2);
        const int kp = (lane & 3) * 2;
        const int nb0 = wn * 16 + (lane >> 2);      // n for B slab 0
        #pragma unroll
        for (int ks = 0; ks < KC; ks += 16) {
            uint32_t ah0 = *(const uint32_t*)&Ah[r0][ks + kp];
            uint32_t ah1 = *(const uint32_t*)&Ah[r0 + 8][ks + kp];
            uint32_t ah2 = *(const uint32_t*)&Ah[r0][ks + kp + 8];
            uint32_t ah3 = *(const uint32_t*)&Ah[r0 + 8][ks + kp + 8];
            uint32_t al0 = *(const uint32_t*)&Al[r0][ks + kp];
            uint32_t al1 = *(const uint32_t*)&Al[r0 + 8][ks + kp];
            uint32_t al2 = *(const uint32_t*)&Al[r0][ks + kp + 8];
            uint32_t al3 = *(const uint32_t*)&Al[r0 + 8][ks + kp + 8];

            // n8 slab 0
            uint32_t bh0 = *(const uint32_t*)&Bh[nb0][ks + kp];
            uint32_t bh1 = *(const uint32_t*)&Bh[nb0][ks + kp + 8];
            uint32_t bl0 = *(const uint32_t*)&Bl[nb0][ks + kp];
            uint32_t bl1 = *(const uint32_t*)&Bl[nb0][ks + kp + 8];
            mma_bf16(acc0, ah0, ah1, ah2, ah3, bh0, bh1);
            mma_bf16(acc0, ah0, ah1, ah2, ah3, bl0, bl1);
            mma_bf16(acc0, al0, al1, al2, al3, bh0, bh1);

            // n8 slab 1
            uint32_t ch0 = *(const uint32_t*)&Bh[nb0 + 8][ks + kp];
            uint32_t ch1 = *(const uint32_t*)&Bh[nb0 + 8][ks + kp + 8];
            uint32_t cl0 = *(const uint32_t*)&Bl[nb0 + 8][ks + kp];
            uint32_t cl1 = *(const uint32_t*)&Bl[nb0 + 8][ks + kp + 8];
            mma_bf16(acc1, ah0, ah1, ah2, ah3, ch0, ch1);
            mma_bf16(acc1, ah0, ah1, ah2, ah3, cl0, cl1);
            mma_bf16(acc1, al0, al1, al2, al3, ch0, ch1);
        }
        __syncthreads();
    }

    // ---- epilogue: write D fragments ----
    {
        int row = m0 + wm * 16 + (lane >> 2);
        int col = n0 + wn * 16 + (lane & 3) * 2;
        *(float2*)&g_T[(size_t)row * FC + col]            = make_float2(acc0[0], acc0[1]);
        *(float2*)&g_T[(size_t)(row + 8) * FC + col]      = make_float2(acc0[2], acc0[3]);
        *(float2*)&g_T[(size_t)row * FC + col + 8]        = make_float2(acc1[0], acc1[1]);
        *(float2*)&g_T[(size_t)(row + 8) * FC + col + 8]  = make_float2(acc1[2], acc1[3]);
    }
}

// ============ K4: y_e = w_e * (T[dst_e] - T[src_e])  (2 elems/thread) ======
__global__ __launch_bounds__(NT)
void k_y(const int* __restrict__ ei, float* __restrict__ y, int E) {
    const int Nel   = E * FC4;
    const int halfN = Nel >> 1;
    int i0 = blockIdx.x * NT + threadIdx.x;
    if (i0 >= halfN) return;
    int i1 = i0 + halfN;

    int e0 = i0 >> 6, c0 = i0 & 63;
    int e1 = i1 >> 6, c1 = i1 & 63;
    int s0 = ei[e0], d0 = ei[E + e0];
    int s1 = ei[e1], d1 = ei[E + e1];
    float w0 = g_w[e0], w1 = g_w[e1];

    float4 vd0 = ((const float4*)g_T)[d0 * FC4 + c0];
    float4 vs0 = ((const float4*)g_T)[s0 * FC4 + c0];
    float4 vd1 = ((const float4*)g_T)[d1 * FC4 + c1];
    float4 vs1 = ((const float4*)g_T)[s1 * FC4 + c1];

    float4 o0, o1;
    o0.x = w0 * (vd0.x - vs0.x); o0.y = w0 * (vd0.y - vs0.y);
    o0.z = w0 * (vd0.z - vs0.z); o0.w = w0 * (vd0.w - vs0.w);
    o1.x = w1 * (vd1.x - vs1.x); o1.y = w1 * (vd1.y - vs1.y);
    o1.z = w1 * (vd1.z - vs1.z); o1.w = w1 * (vd1.w - vs1.w);
    ((float4*)y)[i0] = o0;
    ((float4*)y)[i1] = o1;
}

// ---------------- launch ---------------------------------------------------
extern "C" void kernel_launch(void* const* d_in, const int* in_sizes, int n_in,
                              void* d_out, int out_size) {
    const float* x     = (const float*)d_in[0];   // [E, 256]
    const float* W     = (const float*)d_in[1];   // [256, 256]
    const int*   ei    = (const int*)d_in[2];     // [2, E]
    const void*  isdir = d_in[3];                 // [E] bool or int32

    int E = in_sizes[2] / 2;
    float* y = (float*)d_out;

    k_zero<<<256, NT>>>();
    k_hist<<<(E + NT - 1) / NT, NT>>>(ei, (const unsigned char*)isdir, E);
    k_scatter<<<(E * FC4 + NT - 1) / NT, NT>>>(x, ei, (const unsigned char*)isdir, E);
    k_gemm<<<128, 256>>>(W);
    k_y<<<((E * FC4 / 2) + NT - 1) / NT, NT>>>(ei, y, E);
}

// round 17
// speedup vs baseline: 1.1092x; 1.1092x over previous
#include <cuda_runtime.h>
#include <cuda_bf16.h>
#include <cstdint>

// Fixed problem shapes: E<=4096, IN=OUT=256, N_NODES=1024
#define MAX_E 4096
#define NN    1024
#define FC    256
#define FC4   64
#define NT    256

// ---------------- global scratch ----------------
__device__ int   g_hist[NN];    // src count low 16 bits, dst count high 16 bits
__device__ int   g_sl[NN];      // self-loop count
__device__ int   g_flags;       // bit0: any nonzero byte, bit1: misaligned nonzero (sticky)
__device__ float g_w[MAX_E];
__device__ float g_t[NN * FC];
__device__ float g_T[NN * FC];
__device__ __nv_bfloat16 g_Wh[FC * FC];   // W split: hi
__device__ __nv_bfloat16 g_Wl[FC * FC];   // W split: lo

__device__ __forceinline__ void red_add_v4(float* p, float a, float b,
                                           float c, float d) {
    asm volatile("red.global.add.v4.f32 [%0], {%1, %2, %3, %4};"
                 :: "l"(p), "f"(a), "f"(b), "f"(c), "f"(d)
                 : "memory");
}

__device__ __forceinline__ void split_bf16(float v, __nv_bfloat16& h,
                                           __nv_bfloat16& l) {
    h = __float2bfloat16(v);
    l = __float2bfloat16(v - __bfloat162float(h));
}

// ============ K0: zero accumulators + hist scratch + split W ===============
__global__ __launch_bounds__(NT)
void k_zero(const float* __restrict__ W) {
    int i = blockIdx.x * NT + threadIdx.x;          // 256 blocks -> 65536
    ((float4*)g_t)[i] = make_float4(0.f, 0.f, 0.f, 0.f);
    if (i < NN) { g_hist[i] = 0; g_sl[i] = 0; }
    // W split: one element per thread (65536 == FC*FC)
    float v = W[i];
    __nv_bfloat16 h, l;
    split_bf16(v, h, l);
    g_Wh[i] = h;
    g_Wl[i] = l;
}

// ============ K1: global histogram + layout flags ==========================
__global__ __launch_bounds__(NT)
void k_hist(const int* __restrict__ ei, const unsigned char* __restrict__ bb,
            int E) {
    int e = blockIdx.x * NT + threadIdx.x;
    if (e >= E) return;
    int s = ei[e], d = ei[E + e];
    atomicAdd(&g_hist[s], 1);
    atomicAdd(&g_hist[d], 0x10000);
    if (s == d) atomicAdd(&g_sl[s], 1);
    unsigned char v = bb[e];
    if (v) atomicOr(&g_flags, (e & 3) ? 3 : 1);
}

// ============ K2: scatter  t[src] -= w*x, t[dst] += w*x  (v4 REDs) =========
__global__ __launch_bounds__(NT)
void k_scatter(const float* __restrict__ x, const int* __restrict__ ei,
               const unsigned char* __restrict__ bb, int E) {
    int i = blockIdx.x * NT + threadIdx.x;
    if (i >= E * FC4) return;
    int e  = i >> 6;
    int c4 = i & 63;

    int s = ei[e], d = ei[E + e];           // warp-uniform loads (broadcast)
    float w = 0.0f;
    if (s != d) {
        int hs = g_hist[s], hd = g_hist[d];
        int deg = (hs & 0xffff) + (hs >> 16)
                + (hd & 0xffff) + (hd >> 16)
                - 2 * (g_sl[s] + g_sl[d]);
        int flags = g_flags;
        int dir;
        if (flags & 2)      dir = bb[e] != 0;               // byte layout
        else if (flags & 1) dir = ((const int*)bb)[e] != 0; // int layout
        else                dir = 0;
        w = (dir ? -1.0f : 1.0f) * rsqrtf((float)deg);
    }
    if (c4 == 0) g_w[e] = w;
    if (w == 0.0f) return;

    float4 v = ((const float4*)x)[e * FC4 + c4];
    float* ps = &g_t[(size_t)s * FC + c4 * 4];
    float* pd = &g_t[(size_t)d * FC + c4 * 4];
    red_add_v4(ps, -w * v.x, -w * v.y, -w * v.z, -w * v.w);
    red_add_v4(pd,  w * v.x,  w * v.y,  w * v.z,  w * v.w);
}

// ============ K3: GEMM  T = t @ W^T  via bf16-split tensor cores ===========
// 128 blocks x 256 threads (8 warps). Tile 32x64. Full K=256 in ONE smem
// phase (~101 KB dynamic smem). D = AhBh + AhBl + AlBh, fp32 accum.
#define SSTR 264      // smem row stride in bf16 (132 words; 132%32=4 -> conflict-free)

__device__ __forceinline__ void mma_bf16(float c[4], uint32_t a0, uint32_t a1,
                                         uint32_t a2, uint32_t a3,
                                         uint32_t b0, uint32_t b1) {
    asm volatile(
        "mma.sync.aligned.m16n8k16.row.col.f32.bf16.bf16.f32 "
        "{%0,%1,%2,%3}, {%4,%5,%6,%7}, {%8,%9}, {%0,%1,%2,%3};"
        : "+f"(c[0]), "+f"(c[1]), "+f"(c[2]), "+f"(c[3])
        : "r"(a0), "r"(a1), "r"(a2), "r"(a3), "r"(b0), "r"(b1));
}

extern __shared__ __nv_bfloat16 g_smem[];

__global__ __launch_bounds__(256)
void k_gemm() {
    __nv_bfloat16* Ah = g_smem;                 // [32][SSTR]
    __nv_bfloat16* Al = Ah + 32 * SSTR;
    __nv_bfloat16* Bh = Al + 32 * SSTR;         // [64][SSTR]
    __nv_bfloat16* Bl = Bh + 64 * SSTR;

    const int tid  = threadIdx.x;
    const int b    = blockIdx.x;
    const int gx   = b & 3, gy = b >> 2;
    const int m0   = gy * 32, n0 = gx * 64;
    const int wid  = tid >> 5;
    const int lane = tid & 31;
    const int wm   = wid >> 2;          // 0..1 : 16-row slab
    const int wn   = wid & 3;           // 0..3 : 16-col slab

    // ---- load + split A (full K): 32x256 fp32 = 2048 float4, 8/thread ----
    {
        #pragma unroll
        for (int r = 0; r < 8; r++) {
            int idx = tid + 256 * r;
            int row = idx >> 6;              // 64 float4 per row
            int kq  = (idx & 63) << 2;
            float4 v = *(const float4*)&g_t[(m0 + row) * FC + kq];
            __nv_bfloat16 h0, l0, h1, l1, h2, l2, h3, l3;
            split_bf16(v.x, h0, l0); split_bf16(v.y, h1, l1);
            split_bf16(v.z, h2, l2); split_bf16(v.w, h3, l3);
            __nv_bfloat16* ph = &Ah[row * SSTR + kq];
            __nv_bfloat16* pl = &Al[row * SSTR + kq];
            ph[0] = h0; ph[1] = h1; ph[2] = h2; ph[3] = h3;
            pl[0] = l0; pl[1] = l1; pl[2] = l2; pl[3] = l3;
        }
        // ---- load pre-split B (full K): 64x256 bf16 x2 = 4096 uint4 ------
        #pragma unroll
        for (int r = 0; r < 8; r++) {
            int idx = tid + 256 * r;         // 0..2047 : Bh
            int n   = idx >> 5;              // 32 uint4 per row
            int kq  = (idx & 31) << 3;       // bf16 offset
            uint4 v = *(const uint4*)&g_Wh[(n0 + n) * FC + kq];
            *(uint4*)&Bh[n * SSTR + kq] = v;
        }
        #pragma unroll
        for (int r = 0; r < 8; r++) {
            int idx = tid + 256 * r;
            int n   = idx >> 5;
            int kq  = (idx & 31) << 3;
            uint4 v = *(const uint4*)&g_Wl[(n0 + n) * FC + kq];
            *(uint4*)&Bl[n * SSTR + kq] = v;
        }
    }
    __syncthreads();

    float acc0[4] = {0.f, 0.f, 0.f, 0.f};
    float acc1[4] = {0.f, 0.f, 0.f, 0.f};

    const int r0  = wm * 16 + (lane >> 2);
    const int kp  = (lane & 3) * 2;
    const int nb0 = wn * 16 + (lane >> 2);

    #pragma unroll
    for (int ks = 0; ks < FC; ks += 16) {
        uint32_t ah0 = *(const uint32_t*)&Ah[r0 * SSTR + ks + kp];
        uint32_t ah1 = *(const uint32_t*)&Ah[(r0 + 8) * SSTR + ks + kp];
        uint32_t ah2 = *(const uint32_t*)&Ah[r0 * SSTR + ks + kp + 8];
        uint32_t ah3 = *(const uint32_t*)&Ah[(r0 + 8) * SSTR + ks + kp + 8];
        uint32_t al0 = *(const uint32_t*)&Al[r0 * SSTR + ks + kp];
        uint32_t al1 = *(const uint32_t*)&Al[(r0 + 8) * SSTR + ks + kp];
        uint32_t al2 = *(const uint32_t*)&Al[r0 * SSTR + ks + kp + 8];
        uint32_t al3 = *(const uint32_t*)&Al[(r0 + 8) * SSTR + ks + kp + 8];

        uint32_t bh0 = *(const uint32_t*)&Bh[nb0 * SSTR + ks + kp];
        uint32_t bh1 = *(const uint32_t*)&Bh[nb0 * SSTR + ks + kp + 8];
        uint32_t bl0 = *(const uint32_t*)&Bl[nb0 * SSTR + ks + kp];
        uint32_t bl1 = *(const uint32_t*)&Bl[nb0 * SSTR + ks + kp + 8];
        mma_bf16(acc0, ah0, ah1, ah2, ah3, bh0, bh1);
        mma_bf16(acc0, ah0, ah1, ah2, ah3, bl0, bl1);
        mma_bf16(acc0, al0, al1, al2, al3, bh0, bh1);

        uint32_t ch0 = *(const uint32_t*)&Bh[(nb0 + 8) * SSTR + ks + kp];
        uint32_t ch1 = *(const uint32_t*)&Bh[(nb0 + 8) * SSTR + ks + kp + 8];
        uint32_t cl0 = *(const uint32_t*)&Bl[(nb0 + 8) * SSTR + ks + kp];
        uint32_t cl1 = *(const uint32_t*)&Bl[(nb0 + 8) * SSTR + ks + kp + 8];
        mma_bf16(acc1, ah0, ah1, ah2, ah3, ch0, ch1);
        mma_bf16(acc1, ah0, ah1, ah2, ah3, cl0, cl1);
        mma_bf16(acc1, al0, al1, al2, al3, ch0, ch1);
    }

    // ---- epilogue: write D fragments ----
    {
        int row = m0 + wm * 16 + (lane >> 2);
        int col = n0 + wn * 16 + (lane & 3) * 2;
        *(float2*)&g_T[(size_t)row * FC + col]            = make_float2(acc0[0], acc0[1]);
        *(float2*)&g_T[(size_t)(row + 8) * FC + col]      = make_float2(acc0[2], acc0[3]);
        *(float2*)&g_T[(size_t)row * FC + col + 8]        = make_float2(acc1[0], acc1[1]);
        *(float2*)&g_T[(size_t)(row + 8) * FC + col + 8]  = make_float2(acc1[2], acc1[3]);
    }
}

// ============ K4: y_e = w_e * (T[dst_e] - T[src_e])  (2 elems/thread) ======
__global__ __launch_bounds__(NT)
void k_y(const int* __restrict__ ei, float* __restrict__ y, int E) {
    const int Nel   = E * FC4;
    const int halfN = Nel >> 1;
    int i0 = blockIdx.x * NT + threadIdx.x;
    if (i0 >= halfN) return;
    int i1 = i0 + halfN;

    int e0 = i0 >> 6, c0 = i0 & 63;
    int e1 = i1 >> 6, c1 = i1 & 63;
    int s0 = ei[e0], d0 = ei[E + e0];
    int s1 = ei[e1], d1 = ei[E + e1];
    float w0 = g_w[e0], w1 = g_w[e1];

    float4 vd0 = ((const float4*)g_T)[d0 * FC4 + c0];
    float4 vs0 = ((const float4*)g_T)[s0 * FC4 + c0];
    float4 vd1 = ((const float4*)g_T)[d1 * FC4 + c1];
    float4 vs1 = ((const float4*)g_T)[s1 * FC4 + c1];

    float4 o0, o1;
    o0.x = w0 * (vd0.x - vs0.x); o0.y = w0 * (vd0.y - vs0.y);
    o0.z = w0 * (vd0.z - vs0.z); o0.w = w0 * (vd0.w - vs0.w);
    o1.x = w1 * (vd1.x - vs1.x); o1.y = w1 * (vd1.y - vs1.y);
    o1.z = w1 * (vd1.z - vs1.z); o1.w = w1 * (vd1.w - vs1.w);
    ((float4*)y)[i0] = o0;
    ((float4*)y)[i1] = o1;
}

// ---------------- launch ---------------------------------------------------
extern "C" void kernel_launch(void* const* d_in, const int* in_sizes, int n_in,
                              void* d_out, int out_size) {
    const float* x     = (const float*)d_in[0];   // [E, 256]
    const float* W     = (const float*)d_in[1];   // [256, 256]
    const int*   ei    = (const int*)d_in[2];     // [2, E]
    const void*  isdir = d_in[3];                 // [E] bool or int32

    int E = in_sizes[2] / 2;
    float* y = (float*)d_out;

    const int gemm_smem = (2 * 32 + 2 * 64) * SSTR * (int)sizeof(__nv_bfloat16);
    cudaFuncSetAttribute(k_gemm, cudaFuncAttributeMaxDynamicSharedMemorySize,
                         gemm_smem);

    k_zero<<<256, NT>>>(W);
    k_hist<<<(E + NT - 1) / NT, NT>>>(ei, (const unsigned char*)isdir, E);
    k_scatter<<<(E * FC4 + NT - 1) / NT, NT>>>(x, ei, (const unsigned char*)isdir, E);
    k_gemm<<<128, 256, gemm_smem>>>();
    k_y<<<((E * FC4 / 2) + NT - 1) / NT, NT>>>(ei, y, E);
}